// round 3
// baseline (speedup 1.0000x reference)
#include <cuda_runtime.h>
#include <math.h>

// Problem dims (fixed per metadata):
// latents  [32, 64, 64, 64]  f32   (B, D, H, W)
// embedding[1024, 64]        f32   (K, D)
// out = concat(vq_loss[1], perplexity[1], out[B,D,H,W], one_hot[N,K])
#define N_TOK   131072      // 32*64*64
#define K_CODES 1024
#define DIM     64

// ---- device scratch (no allocs allowed) ----
__device__ int    g_inds[N_TOK];
__device__ float  g_sqnorm[K_CODES];
__device__ int    g_counts[K_CODES];
__device__ double g_sse;

// ---------------------------------------------------------------------------
__global__ void vq_zero()
{
    int t = threadIdx.x;
    if (t < K_CODES) g_counts[t] = 0;
    if (t == 0) g_sse = 0.0;
}

// B_k = sum_d e_kd^2
__global__ void vq_sqnorm(const float* __restrict__ emb)
{
    int k = threadIdx.x;
    if (k < K_CODES) {
        const float* e = emb + (size_t)k * DIM;
        float s = 0.f;
        #pragma unroll
        for (int d = 0; d < DIM; d++) s = __fmaf_rn(e[d], e[d], s);
        g_sqnorm[k] = s;
    }
}

// ---------------------------------------------------------------------------
// Main fused kernel: per 128-token tile, scan all 1024 codes in 8 chunks of
// 128, computing dist_nk = fl( fl(A_n + B_k) - 2*(x_n . e_k) ) with the
// x.e dot as a sequential fp32 FMA chain over d. Running argmin with
// lowest-index tie-break. Accumulates sum((quantized - x)^2) in double.
//
// dynamic smem layout (floats):
//   xs[64][128]   token tile, d-major           : 8192
//   es[64][128]   emb chunk, d-major            : 8192
//   sQ[1024]      ||e_k||^2                     : 1024
//   sA[128]       ||x_n||^2                     : 128
#define SMEM_FLOATS (8192 + 8192 + 1024 + 128)

__global__ __launch_bounds__(256) void vq_main(const float* __restrict__ lat,
                                               const float* __restrict__ emb)
{
    extern __shared__ float smem[];
    float (*xs)[128] = (float(*)[128])(smem);
    float (*es)[128] = (float(*)[128])(smem + 8192);
    float* sQ = smem + 16384;
    float* sA = smem + 17408;

    const int tid   = threadIdx.x;
    const int tbase = blockIdx.x * 128;       // 1024 blocks
    const int b     = tbase >> 12;            // 4096 tokens per batch image
    const float* latb = lat + (size_t)b * 262144 + (tbase & 4095);

    // load token tile: xs[d][t] = latents[b][d][h][w], 128 consecutive (h,w)
    for (int l = tid; l < 64 * 128; l += 256) {
        int d = l >> 7, t = l & 127;
        xs[d][t] = latb[(size_t)d * 4096 + t];
    }
    for (int l = tid; l < K_CODES; l += 256) sQ[l] = g_sqnorm[l];
    __syncthreads();

    // A_n = ||x||^2 (order-insensitive at argmin level: see analysis)
    if (tid < 128) {
        float a = 0.f;
        #pragma unroll
        for (int d = 0; d < DIM; d++) { float v = xs[d][tid]; a = __fmaf_rn(v, v, a); }
        sA[tid] = a;
    }

    const int tx = tid & 15;   // code lane: codes c = cbase + tx + 16*j
    const int ty = tid >> 4;   // token lane: tokens t = ty + 16*i

    float bestV[8]; int bestI[8];
    #pragma unroll
    for (int i = 0; i < 8; i++) { bestV[i] = 3.4e38f; bestI[i] = 0; }

    for (int kc = 0; kc < 8; kc++) {
        const int cbase = kc << 7;
        __syncthreads();   // prev chunk consumed (also covers sA on kc==0)
        // load emb chunk transposed: es[d][c]; c-fast over threads => STS conflict-free
        for (int l = tid; l < 2048; l += 256) {
            int q = l >> 7, c = l & 127;
            float4 v = *(const float4*)(emb + (size_t)(cbase + c) * DIM + q * 4);
            es[q*4+0][c] = v.x; es[q*4+1][c] = v.y;
            es[q*4+2][c] = v.z; es[q*4+3][c] = v.w;
        }
        __syncthreads();

        float acc[8][8];
        #pragma unroll
        for (int i = 0; i < 8; i++)
            #pragma unroll
            for (int j = 0; j < 8; j++) acc[i][j] = 0.f;

        // 64 independent fp32 FMA chains (8x8 register tile per thread)
        for (int d = 0; d < DIM; d++) {
            float xv[8], ev[8];
            #pragma unroll
            for (int i = 0; i < 8; i++) xv[i] = xs[d][ty + 16*i];
            #pragma unroll
            for (int j = 0; j < 8; j++) ev[j] = es[d][tx + 16*j];
            #pragma unroll
            for (int i = 0; i < 8; i++)
                #pragma unroll
                for (int j = 0; j < 8; j++)
                    acc[i][j] = __fmaf_rn(xv[i], ev[j], acc[i][j]);
        }

        // fold into running argmin; ascending code order within thread,
        // strict < keeps lowest index (matches jnp.argmin tie-break)
        #pragma unroll
        for (int j = 0; j < 8; j++) {
            int code = cbase + tx + 16*j;
            float bq = sQ[code];
            #pragma unroll
            for (int i = 0; i < 8; i++) {
                float t1   = __fadd_rn(sA[ty + 16*i], bq);     // fl(A + B)
                float c2   = __fmul_rn(2.0f, acc[i][j]);       // exact
                float dist = __fsub_rn(t1, c2);                // fl((A+B) - 2C)
                if (dist < bestV[i]) { bestV[i] = dist; bestI[i] = code; }
            }
        }
    }

    // cross-lane reduce over the 16 code lanes (xor stays within 16-group)
    double lsse = 0.0;
    #pragma unroll
    for (int i = 0; i < 8; i++) {
        float v = bestV[i]; int idx = bestI[i];
        #pragma unroll
        for (int o = 1; o < 16; o <<= 1) {
            float ov = __shfl_xor_sync(0xffffffffu, v,   o);
            int   oi = __shfl_xor_sync(0xffffffffu, idx, o);
            if (ov < v || (ov == v && oi < idx)) { v = ov; idx = oi; }
        }
        if (tx == 0) {
            int t = ty + 16*i;
            g_inds[tbase + t] = idx;
            const float* er = emb + (size_t)idx * DIM;
            double s = 0.0;
            #pragma unroll
            for (int d = 0; d < DIM; d++) {
                float diff = er[d] - xs[d][t];
                s += (double)diff * (double)diff;
            }
            lsse += s;
        }
    }
    if (tx == 0) atomicAdd(&g_sse, lsse);
}

// ---------------------------------------------------------------------------
__global__ void vq_hist()
{
    __shared__ int h[K_CODES];
    int t = threadIdx.x;
    h[t] = 0;
    __syncthreads();
    for (int n = blockIdx.x * blockDim.x + t; n < N_TOK; n += gridDim.x * blockDim.x)
        atomicAdd(&h[g_inds[n]], 1);
    __syncthreads();
    if (h[t]) atomicAdd(&g_counts[t], h[t]);
}

// out[b][d][h][w] = embedding[ind[b,h,w]][d]   (8388608 elems, coalesced write)
__global__ void vq_gather(float* __restrict__ out, const float* __restrict__ emb)
{
    int i = blockIdx.x * blockDim.x + threadIdx.x;
    int w = i & 63, h = (i >> 6) & 63, d = (i >> 12) & 63, b = i >> 18;
    int n = (b << 12) | (h << 6) | w;
    out[i] = __ldg(emb + (size_t)g_inds[n] * DIM + d);
}

// one_hot writer: one block per token row. float2 stores (8B) — the region
// base is out+2 floats, i.e. 8-byte aligned only; float4 would trap (R1 bug).
// Fully writes the row (zeros + the single 1.0), no memset needed.
__global__ __launch_bounds__(256) void vq_onehot(float* __restrict__ oh)
{
    const int n   = blockIdx.x;
    const int ind = g_inds[n];
    float2* row = (float2*)(oh + (size_t)n * K_CODES);
    const int p2  = ind >> 1;          // float2 slot holding the one
    const int sub = ind & 1;
    #pragma unroll
    for (int r = 0; r < 2; r++) {
        int idx2 = threadIdx.x + (r << 8);      // 0..511
        float2 v = make_float2(0.f, 0.f);
        if (idx2 == p2) ((float*)&v)[sub] = 1.0f;
        row[idx2] = v;
    }
}

// scalars: vq_loss = fl(fl(mse*0.25) + mse) ; perplexity = exp(-sum p*log(p+1e-10))
__global__ void vq_final(float* __restrict__ out0)
{
    __shared__ float partial[K_CODES];
    int k = threadIdx.x;
    float p = (float)g_counts[k] * (1.0f / 131072.0f);   // exact (pow2 divide)
    partial[k] = p * logf(p + 1e-10f);
    __syncthreads();
    for (int s = 512; s > 0; s >>= 1) {
        if (k < s) partial[k] += partial[k + s];
        __syncthreads();
    }
    if (k == 0) {
        float mse = (float)(g_sse / 8388608.0);
        out0[0] = __fadd_rn(__fmul_rn(mse, 0.25f), mse);
        out0[1] = expf(-partial[0]);
    }
}

// ---------------------------------------------------------------------------
extern "C" void kernel_launch(void* const* d_in, const int* in_sizes, int n_in,
                              void* d_out, int out_size)
{
    const float* lat = (const float*)d_in[0];   // [32,64,64,64]
    const float* emb = (const float*)d_in[1];   // [1024,64]
    float* out = (float*)d_out;

    (void)in_sizes; (void)n_in;

    cudaFuncSetAttribute(vq_main, cudaFuncAttributeMaxDynamicSharedMemorySize,
                         SMEM_FLOATS * (int)sizeof(float));

    vq_zero  <<<1, 1024>>>();
    vq_sqnorm<<<1, 1024>>>(emb);
    vq_main  <<<1024, 256, SMEM_FLOATS * sizeof(float)>>>(lat, emb);
    vq_hist  <<<128, 1024>>>();
    vq_gather<<<32768, 256>>>(out + 2, emb);

    if ((long long)out_size >= 2LL + 8388608LL + (long long)N_TOK * K_CODES)
        vq_onehot<<<N_TOK, 256>>>(out + 2 + 8388608);

    vq_final <<<1, 1024>>>(out);
}

// round 7
// speedup vs baseline: 1.4422x; 1.4422x over previous
#include <cuda_runtime.h>
#include <math.h>

// latents  [32, 64, 64, 64] f32 (B,D,H,W); embedding [1024, 64] f32
// out = concat(vq_loss[1], perplexity[1], out[B,D,H,W], one_hot[N,K])
#define N_TOK   131072
#define K_CODES 1024
#define DIM     64

__device__ int    g_inds[N_TOK];
__device__ float  g_sqnorm[K_CODES];
__device__ int    g_counts[K_CODES];
__device__ double g_sse;

// ---------------------------------------------------------------------------
__global__ void vq_zero()
{
    int t = threadIdx.x;
    if (t < K_CODES) g_counts[t] = 0;
    if (t == 0) g_sse = 0.0;
}

__global__ void vq_sqnorm(const float* __restrict__ emb)
{
    int k = threadIdx.x;
    if (k < K_CODES) {
        const float* e = emb + (size_t)k * DIM;
        float s = 0.f;
        #pragma unroll
        for (int d = 0; d < DIM; d++) s = __fmaf_rn(e[d], e[d], s);
        g_sqnorm[k] = s;
    }
}

// ---------------------------------------------------------------------------
// vq_main: 512 threads, 128 tokens/block, 1024 blocks. Codes scanned in 8
// chunks of 128. Per thread: 8 tokens x 4 codes. dist arithmetic identical
// to the R3-passing kernel: sequential-d fp32 FMA chain per (token,code),
// then fl( fl(A+B) - 2*acc ), strict-< ascending-code argmin.
// Epilogue additionally writes the one_hot rows (fused: stores hide under
// the FFMA-bound compute of concurrent blocks).
// smem (floats): xs[64][128]=8192, es[64][128]=8192, sQ=1024, sA=128
#define SMEM_FLOATS (8192 + 8192 + 1024 + 128)

__global__ __launch_bounds__(512, 1) void vq_main(const float* __restrict__ lat,
                                                  const float* __restrict__ emb,
                                                  float* __restrict__ oh,
                                                  int write_oh)
{
    extern __shared__ float smem[];
    float* xs = smem;            // xs[d*128 + t]
    float* es = smem + 8192;     // es[d*128 + c]
    float* sQ = smem + 16384;
    float* sA = smem + 17408;

    const int tid   = threadIdx.x;
    const int tbase = blockIdx.x * 128;
    const int b     = tbase >> 12;
    const float* latb = lat + (size_t)b * 262144 + (tbase & 4095);

    // token tile: xs[d][t] = latents[b][d][.], coalesced gmem, conflict-free STS
    for (int l = tid; l < 8192; l += 512) {
        int d = l >> 7, t = l & 127;
        xs[d * 128 + t] = latb[(size_t)d * 4096 + t];
    }
    for (int l = tid; l < K_CODES; l += 512) sQ[l] = g_sqnorm[l];
    __syncthreads();

    if (tid < 128) {
        float a = 0.f;
        #pragma unroll
        for (int d = 0; d < DIM; d++) { float v = xs[d * 128 + tid]; a = __fmaf_rn(v, v, a); }
        sA[tid] = a;
    }

    const int cl = tid & 31;         // code lane: codes cbase + cl + 32*j
    const int tl = tid >> 5;         // token lane (warp id): tokens tl + 16*i

    // prefetch mapping: each thread owns column c = tid&127, qbase = tid>>7
    const int pc = tid & 127;
    const int pq = tid >> 7;         // 0..3 ; q = pq + 4*s for s=0..3

    float bestV[8]; int bestI[8];
    #pragma unroll
    for (int i = 0; i < 8; i++) { bestV[i] = 3.4e38f; bestI[i] = 0; }

    // prefetch chunk 0 into registers
    float4 pv[4];
    #pragma unroll
    for (int s = 0; s < 4; s++)
        pv[s] = *(const float4*)(emb + (size_t)pc * DIM + (pq + 4 * s) * 4);

    for (int kc = 0; kc < 8; kc++) {
        const int cbase = kc << 7;
        __syncthreads();             // everyone done reading es from prev chunk
        // store prefetched chunk (transposed, conflict-free: c fast over lanes)
        #pragma unroll
        for (int s = 0; s < 4; s++) {
            int q = pq + 4 * s;
            es[(q * 4 + 0) * 128 + pc] = pv[s].x;
            es[(q * 4 + 1) * 128 + pc] = pv[s].y;
            es[(q * 4 + 2) * 128 + pc] = pv[s].z;
            es[(q * 4 + 3) * 128 + pc] = pv[s].w;
        }
        __syncthreads();
        // issue prefetch for next chunk (latency hidden under compute)
        if (kc < 7) {
            const float* src = emb + (size_t)(cbase + 128 + pc) * DIM;
            #pragma unroll
            for (int s = 0; s < 4; s++)
                pv[s] = *(const float4*)(src + (pq + 4 * s) * 4);
        }

        float acc[8][4];
        #pragma unroll
        for (int i = 0; i < 8; i++)
            #pragma unroll
            for (int j = 0; j < 4; j++) acc[i][j] = 0.f;

        #pragma unroll 4
        for (int d = 0; d < DIM; d++) {
            float xv[8], ev[4];
            #pragma unroll
            for (int i = 0; i < 8; i++) xv[i] = xs[d * 128 + tl + 16 * i];   // broadcast
            #pragma unroll
            for (int j = 0; j < 4; j++) ev[j] = es[d * 128 + cl + 32 * j];   // conflict-free
            #pragma unroll
            for (int i = 0; i < 8; i++)
                #pragma unroll
                for (int j = 0; j < 4; j++)
                    acc[i][j] = __fmaf_rn(xv[i], ev[j], acc[i][j]);
        }

        // fold: ascending code order within thread; strict < keeps lowest index
        #pragma unroll
        for (int j = 0; j < 4; j++) {
            int code = cbase + cl + 32 * j;
            float bq = sQ[code];
            #pragma unroll
            for (int i = 0; i < 8; i++) {
                float t1   = __fadd_rn(sA[tl + 16 * i], bq);
                float c2   = __fmul_rn(2.0f, acc[i][j]);
                float dist = __fsub_rn(t1, c2);
                if (dist < bestV[i]) { bestV[i] = dist; bestI[i] = code; }
            }
        }
    }

    // per-token winner: full-warp reduce over the 32 code lanes
    double lsse = 0.0;
    #pragma unroll
    for (int i = 0; i < 8; i++) {
        float v = bestV[i]; int idx = bestI[i];
        #pragma unroll
        for (int o = 16; o >= 1; o >>= 1) {
            float ov = __shfl_xor_sync(0xffffffffu, v,   o);
            int   oi = __shfl_xor_sync(0xffffffffu, idx, o);
            if (ov < v || (ov == v && oi < idx)) { v = ov; idx = oi; }
        }
        // all lanes hold the winner: parallel SSE (2 dims per lane)
        int t = tl + 16 * i;
        const float* er = emb + (size_t)idx * DIM;
        float d0 = er[cl]      - xs[cl * 128 + t];
        float d1 = er[cl + 32] - xs[(cl + 32) * 128 + t];
        double s = (double)d0 * d0 + (double)d1 * d1;
        #pragma unroll
        for (int o = 16; o >= 1; o >>= 1)
            s += __shfl_xor_sync(0xffffffffu, s, o);
        if (cl == 0) {
            g_inds[tbase + t] = idx;
            atomicAdd(&g_counts[idx], 1);
            lsse += s;
        }
        // fused one_hot row write: warp exclusively owns this row.
        // float2 (8B) stores — region base is 8B-aligned only (float4 traps).
        if (write_oh) {
            float2* row = (float2*)(oh + (size_t)(tbase + t) * K_CODES);
            const int p2  = idx >> 1;
            const int sub = idx & 1;
            #pragma unroll
            for (int r = 0; r < 16; r++) {
                int slot = cl + 32 * r;               // 0..511
                float2 vv = make_float2(0.f, 0.f);
                if (slot == p2) ((float*)&vv)[sub] = 1.0f;
                __stcs(row + slot, vv);
            }
        }
    }
    if (cl == 0) atomicAdd(&g_sse, lsse);
}

// ---------------------------------------------------------------------------
// out[b][d][h][w] = embedding[ind[b,h,w]][d]
__global__ void vq_gather(float* __restrict__ out, const float* __restrict__ emb)
{
    int i = blockIdx.x * blockDim.x + threadIdx.x;
    int w = i & 63, h = (i >> 6) & 63, d = (i >> 12) & 63, b = i >> 18;
    int n = (b << 12) | (h << 6) | w;
    out[i] = __ldg(emb + (size_t)g_inds[n] * DIM + d);
}

// scalars
__global__ void vq_final(float* __restrict__ out0)
{
    __shared__ float partial[K_CODES];
    int k = threadIdx.x;
    float p = (float)g_counts[k] * (1.0f / 131072.0f);
    partial[k] = p * logf(p + 1e-10f);
    __syncthreads();
    for (int s = 512; s > 0; s >>= 1) {
        if (k < s) partial[k] += partial[k + s];
        __syncthreads();
    }
    if (k == 0) {
        float mse = (float)(g_sse / 8388608.0);
        out0[0] = __fadd_rn(__fmul_rn(mse, 0.25f), mse);
        out0[1] = expf(-partial[0]);
    }
}

// ---------------------------------------------------------------------------
extern "C" void kernel_launch(void* const* d_in, const int* in_sizes, int n_in,
                              void* d_out, int out_size)
{
    const float* lat = (const float*)d_in[0];
    const float* emb = (const float*)d_in[1];
    float* out = (float*)d_out;
    (void)in_sizes; (void)n_in;

    cudaFuncSetAttribute(vq_main, cudaFuncAttributeMaxDynamicSharedMemorySize,
                         SMEM_FLOATS * (int)sizeof(float));

    int write_oh = (long long)out_size >= 2LL + 8388608LL + (long long)N_TOK * K_CODES;
    float* oh = out + 2 + 8388608;

    vq_zero  <<<1, 1024>>>();
    vq_sqnorm<<<1, 1024>>>(emb);
    vq_main  <<<1024, 512, SMEM_FLOATS * sizeof(float)>>>(lat, emb, oh, write_oh);
    vq_gather<<<32768, 256>>>(out + 2, emb);
    vq_final <<<1, 1024>>>(out);
}

// round 8
// speedup vs baseline: 1.7533x; 1.2157x over previous
#include <cuda_runtime.h>
#include <math.h>

// latents  [32, 64, 64, 64] f32 (B,D,H,W); embedding [1024, 64] f32
// out = concat(vq_loss[1], perplexity[1], out[B,D,H,W], one_hot[N,K])
#define N_TOK   131072
#define K_CODES 1024
#define DIM     64

__device__ int    g_inds[N_TOK];
__device__ float  g_sqnorm[K_CODES];
__device__ int    g_counts[K_CODES];
__device__ double g_sse;

// packed fp32x2 FMA: per-half IEEE fp32 FMA, identical rounding to scalar FFMA
#define FMA_F32X2(acc, a, b) \
    asm("fma.rn.f32x2 %0, %1, %2, %0;" : "+l"(acc) : "l"(a), "l"(b))
#define PACK2_SAME(out, r) \
    asm("mov.b64 %0, {%1, %1};" : "=l"(out) : "r"(r))
#define UNPACK2(lo, hi, v) \
    asm("mov.b64 {%0, %1}, %2;" : "=r"(lo), "=r"(hi) : "l"(v))

// ---------------------------------------------------------------------------
__global__ void vq_zero()
{
    int t = threadIdx.x;
    if (t < K_CODES) g_counts[t] = 0;
    if (t == 0) g_sse = 0.0;
}

__global__ void vq_sqnorm(const float* __restrict__ emb)
{
    int k = threadIdx.x;
    if (k < K_CODES) {
        const float* e = emb + (size_t)k * DIM;
        float s = 0.f;
        #pragma unroll
        for (int d = 0; d < DIM; d++) s = __fmaf_rn(e[d], e[d], s);
        g_sqnorm[k] = s;
    }
}

// ---------------------------------------------------------------------------
// vq_main: 512 threads, 128 tokens/block, 1024 blocks, 8 chunks of 128 codes.
// Warp w owns tokens 8w..8w+7 as 4 adjacent pairs; per thread 4 pairs x 4
// codes accumulated with fma.rn.f32x2 (2 independent fp32 chains per reg).
// Each (token,code) chain's rounding order is IDENTICAL to the scalar R3/R7
// kernel: sequential fp32 FMA over d, then fl( fl(A+B) - 2*acc ), strict-<
// ascending-code argmin. Fused one_hot epilogue (float2 stores, 8B-aligned).
// smem (floats): xs[64][128]=8192, es[64][128]=8192, sQ=1024, sA=128
#define SMEM_FLOATS (8192 + 8192 + 1024 + 128)

__global__ __launch_bounds__(512, 1) void vq_main(const float* __restrict__ lat,
                                                  const float* __restrict__ emb,
                                                  float* __restrict__ oh,
                                                  int write_oh)
{
    extern __shared__ float smem[];
    float* xs = smem;            // xs[d*128 + t]
    float* es = smem + 8192;     // es[d*128 + c]
    float* sQ = smem + 16384;
    float* sA = smem + 17408;

    const int tid   = threadIdx.x;
    const int tbase = blockIdx.x * 128;
    const int b     = tbase >> 12;
    const float* latb = lat + (size_t)b * 262144 + (tbase & 4095);

    // token tile: xs[d][t] = latents[b][d][.], coalesced gmem, conflict-free STS
    for (int l = tid; l < 8192; l += 512) {
        int d = l >> 7, t = l & 127;
        xs[d * 128 + t] = latb[(size_t)d * 4096 + t];
    }
    for (int l = tid; l < K_CODES; l += 512) sQ[l] = g_sqnorm[l];
    __syncthreads();

    if (tid < 128) {
        float a = 0.f;
        #pragma unroll
        for (int d = 0; d < DIM; d++) { float v = xs[d * 128 + tid]; a = __fmaf_rn(v, v, a); }
        sA[tid] = a;
    }

    const int cl = tid & 31;          // code lane: codes cbase + cl + 32*j
    const int tw = (tid >> 5) * 8;    // warp token base: tokens tw..tw+7

    // prefetch mapping: each thread owns emb column c = tid&127, qbase = tid>>7
    const int pc = tid & 127;
    const int pq = tid >> 7;          // 0..3 ; q = pq + 4*s

    float bestV[8]; int bestI[8];
    #pragma unroll
    for (int i = 0; i < 8; i++) { bestV[i] = 3.4e38f; bestI[i] = 0; }

    float4 pv[4];
    #pragma unroll
    for (int s = 0; s < 4; s++)
        pv[s] = *(const float4*)(emb + (size_t)pc * DIM + (pq + 4 * s) * 4);

    for (int kc = 0; kc < 8; kc++) {
        const int cbase = kc << 7;
        __syncthreads();
        #pragma unroll
        for (int s = 0; s < 4; s++) {
            int q = pq + 4 * s;
            es[(q * 4 + 0) * 128 + pc] = pv[s].x;
            es[(q * 4 + 1) * 128 + pc] = pv[s].y;
            es[(q * 4 + 2) * 128 + pc] = pv[s].z;
            es[(q * 4 + 3) * 128 + pc] = pv[s].w;
        }
        __syncthreads();
        if (kc < 7) {
            const float* src = emb + (size_t)(cbase + 128 + pc) * DIM;
            #pragma unroll
            for (int s = 0; s < 4; s++)
                pv[s] = *(const float4*)(src + (pq + 4 * s) * 4);
        }

        unsigned long long acc2[4][4];   // [token pair p][code j], 2 chains/reg
        #pragma unroll
        for (int p = 0; p < 4; p++)
            #pragma unroll
            for (int j = 0; j < 4; j++) acc2[p][j] = 0ull;

        #pragma unroll 4
        for (int d = 0; d < DIM; d++) {
            // token pairs (tw+2p, tw+2p+1): 8B-aligned, same-address broadcast
            unsigned long long xv2[4];
            #pragma unroll
            for (int p = 0; p < 4; p++)
                xv2[p] = *(const unsigned long long*)(xs + d * 128 + tw + 2 * p);
            // codes: lane-consecutive LDS, duplicate into both halves
            unsigned long long ev2[4];
            #pragma unroll
            for (int j = 0; j < 4; j++) {
                float e = es[d * 128 + cl + 32 * j];
                PACK2_SAME(ev2[j], __float_as_uint(e));
            }
            #pragma unroll
            for (int p = 0; p < 4; p++)
                #pragma unroll
                for (int j = 0; j < 4; j++)
                    FMA_F32X2(acc2[p][j], xv2[p], ev2[j]);
        }

        // fold: ascending code order; strict < keeps lowest index
        #pragma unroll
        for (int j = 0; j < 4; j++) {
            int code = cbase + cl + 32 * j;
            float bq = sQ[code];
            #pragma unroll
            for (int p = 0; p < 4; p++) {
                unsigned lo, hi;
                UNPACK2(lo, hi, acc2[p][j]);
                {   // token tw + 2p
                    float t1   = __fadd_rn(sA[tw + 2 * p], bq);
                    float dist = __fsub_rn(t1, __fmul_rn(2.0f, __uint_as_float(lo)));
                    if (dist < bestV[2 * p]) { bestV[2 * p] = dist; bestI[2 * p] = code; }
                }
                {   // token tw + 2p + 1
                    float t1   = __fadd_rn(sA[tw + 2 * p + 1], bq);
                    float dist = __fsub_rn(t1, __fmul_rn(2.0f, __uint_as_float(hi)));
                    if (dist < bestV[2 * p + 1]) { bestV[2 * p + 1] = dist; bestI[2 * p + 1] = code; }
                }
            }
        }
    }

    // per-token winner: full-warp reduce over the 32 code lanes
    double lsse = 0.0;
    #pragma unroll
    for (int i = 0; i < 8; i++) {
        float v = bestV[i]; int idx = bestI[i];
        #pragma unroll
        for (int o = 16; o >= 1; o >>= 1) {
            float ov = __shfl_xor_sync(0xffffffffu, v,   o);
            int   oi = __shfl_xor_sync(0xffffffffu, idx, o);
            if (ov < v || (ov == v && oi < idx)) { v = ov; idx = oi; }
        }
        int t = tw + i;
        const float* er = emb + (size_t)idx * DIM;
        float d0 = er[cl]      - xs[cl * 128 + t];
        float d1 = er[cl + 32] - xs[(cl + 32) * 128 + t];
        double s = (double)d0 * d0 + (double)d1 * d1;
        #pragma unroll
        for (int o = 16; o >= 1; o >>= 1)
            s += __shfl_xor_sync(0xffffffffu, s, o);
        if (cl == 0) {
            g_inds[tbase + t] = idx;
            atomicAdd(&g_counts[idx], 1);
            lsse += s;
        }
        // fused one_hot row write (warp exclusively owns row; float2 = 8B ok)
        if (write_oh) {
            float2* row = (float2*)(oh + (size_t)(tbase + t) * K_CODES);
            const int p2  = idx >> 1;
            const int sub = idx & 1;
            #pragma unroll
            for (int r = 0; r < 16; r++) {
                int slot = cl + 32 * r;
                float2 vv = make_float2(0.f, 0.f);
                if (slot == p2) ((float*)&vv)[sub] = 1.0f;
                __stcs(row + slot, vv);
            }
        }
    }
    if (cl == 0) atomicAdd(&g_sse, lsse);
}

// ---------------------------------------------------------------------------
// gather with smem transpose: block = 64 tokens, coalesced on both sides.
__global__ __launch_bounds__(256) void vq_gather(float* __restrict__ out,
                                                 const float* __restrict__ emb)
{
    __shared__ float sm[64 * 65];
    __shared__ int   sidx[64];
    const int tid = threadIdx.x;
    const int n0  = blockIdx.x * 64;

    if (tid < 64) sidx[tid] = g_inds[n0 + tid];
    __syncthreads();

    // stage 64 emb rows (float4 reads, 65-stride scatter into smem)
    for (int l = tid; l < 64 * 16; l += 256) {
        int row = l >> 4, c = l & 15;
        float4 v = ((const float4*)(emb + (size_t)sidx[row] * DIM))[c];
        float* dst = sm + row * 65 + c * 4;
        dst[0] = v.x; dst[1] = v.y; dst[2] = v.z; dst[3] = v.w;
    }
    __syncthreads();

    // write out[b][d][hw0 + t] : 64 consecutive floats per d (coalesced)
    const int bb  = n0 >> 12;
    const int hw0 = n0 & 4095;
    float* ob = out + (size_t)bb * 262144 + hw0;
    for (int m = 0; m < 16; m++) {
        int idx = m * 256 + tid;
        int t = idx & 63, d = idx >> 6;
        ob[(size_t)d * 4096 + t] = sm[t * 65 + d];
    }
}

// scalars
__global__ void vq_final(float* __restrict__ out0)
{
    __shared__ float partial[K_CODES];
    int k = threadIdx.x;
    float p = (float)g_counts[k] * (1.0f / 131072.0f);
    partial[k] = p * logf(p + 1e-10f);
    __syncthreads();
    for (int s = 512; s > 0; s >>= 1) {
        if (k < s) partial[k] += partial[k + s];
        __syncthreads();
    }
    if (k == 0) {
        float mse = (float)(g_sse / 8388608.0);
        out0[0] = __fadd_rn(__fmul_rn(mse, 0.25f), mse);
        out0[1] = expf(-partial[0]);
    }
}

// ---------------------------------------------------------------------------
extern "C" void kernel_launch(void* const* d_in, const int* in_sizes, int n_in,
                              void* d_out, int out_size)
{
    const float* lat = (const float*)d_in[0];
    const float* emb = (const float*)d_in[1];
    float* out = (float*)d_out;
    (void)in_sizes; (void)n_in;

    cudaFuncSetAttribute(vq_main, cudaFuncAttributeMaxDynamicSharedMemorySize,
                         SMEM_FLOATS * (int)sizeof(float));

    int write_oh = (long long)out_size >= 2LL + 8388608LL + (long long)N_TOK * K_CODES;
    float* oh = out + 2 + 8388608;

    vq_zero  <<<1, 1024>>>();
    vq_sqnorm<<<1, 1024>>>(emb);
    vq_main  <<<1024, 512, SMEM_FLOATS * sizeof(float)>>>(lat, emb, oh, write_oh);
    vq_gather<<<N_TOK / 64, 256>>>(out + 2, emb);
    vq_final <<<1, 1024>>>(out);
}

// round 11
// speedup vs baseline: 1.7955x; 1.0241x over previous
#include <cuda_runtime.h>
#include <math.h>

// latents  [32, 64, 64, 64] f32 (B,D,H,W); embedding [1024, 64] f32
// out = concat(vq_loss[1], perplexity[1], out[B,D,H,W], one_hot[N,K])
#define N_TOK   131072
#define K_CODES 1024
#define DIM     64

__device__ int    g_inds[N_TOK];
__device__ float  g_sqnorm[K_CODES];
__device__ int    g_counts[K_CODES];
__device__ double g_sse;

// packed fp32x2 FMA: per-half IEEE fp32 FMA, identical rounding to scalar FFMA
#define FMA_F32X2(acc, a, b) \
    asm("fma.rn.f32x2 %0, %1, %2, %0;" : "+l"(acc) : "l"(a), "l"(b))
#define PACK2_SAME(out, r) \
    asm("mov.b64 %0, {%1, %1};" : "=l"(out) : "r"(r))
#define UNPACK2(lo, hi, v) \
    asm("mov.b64 {%0, %1}, %2;" : "=r"(lo), "=r"(hi) : "l"(v))

// ---------------------------------------------------------------------------
__global__ void vq_zero()
{
    int t = threadIdx.x;
    if (t < K_CODES) g_counts[t] = 0;
    if (t == 0) g_sse = 0.0;
}

__global__ void vq_sqnorm(const float* __restrict__ emb)
{
    int k = threadIdx.x;
    if (k < K_CODES) {
        const float* e = emb + (size_t)k * DIM;
        float s = 0.f;
        #pragma unroll
        for (int d = 0; d < DIM; d++) s = __fmaf_rn(e[d], e[d], s);
        g_sqnorm[k] = s;
    }
}

// ---------------------------------------------------------------------------
// vq_main: 512 threads, 128 tokens/block, 1024 blocks, 4 chunks of 256 codes.
// Warp w owns tokens 8w..8w+7 as 4 adjacent pairs; per thread 4 pairs x 8
// codes accumulated with fma.rn.f32x2 (2 independent fp32 chains per reg).
// Each (token,code) chain's rounding is IDENTICAL to the scalar R3 kernel:
// sequential fp32 FMA over d, then fl( fl(A+B) - 2*acc ), strict-< ascending-
// code argmin. Fused one_hot epilogue (float2 stores, 8B-aligned base).
// smem (floats): xs[64][128]=8192, es[64][256]=16384, sQ=1024, sA=128
#define SMEM_FLOATS (8192 + 16384 + 1024 + 128)

__global__ __launch_bounds__(512, 1) void vq_main(const float* __restrict__ lat,
                                                  const float* __restrict__ emb,
                                                  float* __restrict__ oh,
                                                  int write_oh)
{
    extern __shared__ float smem[];
    float* xs = smem;            // xs[d*128 + t]
    float* es = smem + 8192;     // es[d*256 + c]
    float* sQ = smem + 24576;
    float* sA = smem + 25600;

    const int tid   = threadIdx.x;
    const int tbase = blockIdx.x * 128;
    const int b     = tbase >> 12;
    const float* latb = lat + (size_t)b * 262144 + (tbase & 4095);

    // token tile: xs[d][t] coalesced gmem, conflict-free STS
    for (int l = tid; l < 8192; l += 512) {
        int d = l >> 7, t = l & 127;
        xs[d * 128 + t] = latb[(size_t)d * 4096 + t];
    }
    for (int l = tid; l < K_CODES; l += 512) sQ[l] = g_sqnorm[l];
    __syncthreads();

    if (tid < 128) {
        float a = 0.f;
        #pragma unroll
        for (int d = 0; d < DIM; d++) { float v = xs[d * 128 + tid]; a = __fmaf_rn(v, v, a); }
        sA[tid] = a;
    }

    const int cl = tid & 31;          // code lane: codes cbase + cl + 32*j, j<8
    const int tw = (tid >> 5) * 8;    // warp token base: tokens tw..tw+7

    // es fill mapping: thread owns code column c = tid&255, dim half = tid>>8
    const int fc = tid & 255;
    const int fh = (tid >> 8) * 32;   // dims [fh, fh+32)

    float bestV[8]; int bestI[8];
    #pragma unroll
    for (int i = 0; i < 8; i++) { bestV[i] = 3.4e38f; bestI[i] = 0; }

    for (int kc = 0; kc < 4; kc++) {
        const int cbase = kc << 8;
        __syncthreads();              // prev chunk fully consumed
        // load 256-code chunk (emb is L2-hot: 256KB shared by all SMs) and
        // store transposed: es[d][c], c fast over lanes => conflict-free STS
        {
            const float* src = emb + (size_t)(cbase + fc) * DIM + fh;
            #pragma unroll
            for (int s = 0; s < 8; s++) {
                float4 v = *(const float4*)(src + s * 4);
                es[(fh + s * 4 + 0) * 256 + fc] = v.x;
                es[(fh + s * 4 + 1) * 256 + fc] = v.y;
                es[(fh + s * 4 + 2) * 256 + fc] = v.z;
                es[(fh + s * 4 + 3) * 256 + fc] = v.w;
            }
        }
        __syncthreads();

        unsigned long long acc2[4][8];   // [token pair p][code j]
        #pragma unroll
        for (int p = 0; p < 4; p++)
            #pragma unroll
            for (int j = 0; j < 8; j++) acc2[p][j] = 0ull;

        #pragma unroll 4
        for (int d = 0; d < DIM; d++) {
            unsigned long long xv2[4];
            #pragma unroll
            for (int p = 0; p < 4; p++)       // 8B broadcast loads
                xv2[p] = *(const unsigned long long*)(xs + d * 128 + tw + 2 * p);
            unsigned long long ev2[8];
            #pragma unroll
            for (int j = 0; j < 8; j++) {     // lane-consecutive, conflict-free
                float e = es[d * 256 + cl + 32 * j];
                PACK2_SAME(ev2[j], __float_as_uint(e));
            }
            #pragma unroll
            for (int p = 0; p < 4; p++)
                #pragma unroll
                for (int j = 0; j < 8; j++)
                    FMA_F32X2(acc2[p][j], xv2[p], ev2[j]);
        }

        // fold: ascending code order; strict < keeps lowest index
        #pragma unroll
        for (int j = 0; j < 8; j++) {
            int code = cbase + cl + 32 * j;
            float bq = sQ[code];
            #pragma unroll
            for (int p = 0; p < 4; p++) {
                unsigned lo, hi;
                UNPACK2(lo, hi, acc2[p][j]);
                {
                    float t1   = __fadd_rn(sA[tw + 2 * p], bq);
                    float dist = __fsub_rn(t1, __fmul_rn(2.0f, __uint_as_float(lo)));
                    if (dist < bestV[2 * p]) { bestV[2 * p] = dist; bestI[2 * p] = code; }
                }
                {
                    float t1   = __fadd_rn(sA[tw + 2 * p + 1], bq);
                    float dist = __fsub_rn(t1, __fmul_rn(2.0f, __uint_as_float(hi)));
                    if (dist < bestV[2 * p + 1]) { bestV[2 * p + 1] = dist; bestI[2 * p + 1] = code; }
                }
            }
        }
    }

    // per-token winner: full-warp reduce over the 32 code lanes
    double lsse = 0.0;
    #pragma unroll
    for (int i = 0; i < 8; i++) {
        float v = bestV[i]; int idx = bestI[i];
        #pragma unroll
        for (int o = 16; o >= 1; o >>= 1) {
            float ov = __shfl_xor_sync(0xffffffffu, v,   o);
            int   oi = __shfl_xor_sync(0xffffffffu, idx, o);
            if (ov < v || (ov == v && oi < idx)) { v = ov; idx = oi; }
        }
        int t = tw + i;
        const float* er = emb + (size_t)idx * DIM;
        float d0 = er[cl]      - xs[cl * 128 + t];
        float d1 = er[cl + 32] - xs[(cl + 32) * 128 + t];
        double s = (double)d0 * d0 + (double)d1 * d1;
        #pragma unroll
        for (int o = 16; o >= 1; o >>= 1)
            s += __shfl_xor_sync(0xffffffffu, s, o);
        if (cl == 0) {
            g_inds[tbase + t] = idx;
            atomicAdd(&g_counts[idx], 1);
            lsse += s;
        }
        // fused one_hot row write (warp exclusively owns row; float2 = 8B ok)
        if (write_oh) {
            float2* row = (float2*)(oh + (size_t)(tbase + t) * K_CODES);
            const int p2  = idx >> 1;
            const int sub = idx & 1;
            #pragma unroll
            for (int r = 0; r < 16; r++) {
                int slot = cl + 32 * r;
                float2 vv = make_float2(0.f, 0.f);
                if (slot == p2) ((float*)&vv)[sub] = 1.0f;
                __stcs(row + slot, vv);
            }
        }
    }
    if (cl == 0) atomicAdd(&g_sse, lsse);
}

// ---------------------------------------------------------------------------
// gather with smem transpose: block = 64 tokens, coalesced on both sides.
__global__ __launch_bounds__(256) void vq_gather(float* __restrict__ out,
                                                 const float* __restrict__ emb)
{
    __shared__ float sm[64 * 65];
    __shared__ int   sidx[64];
    const int tid = threadIdx.x;
    const int n0  = blockIdx.x * 64;

    if (tid < 64) sidx[tid] = g_inds[n0 + tid];
    __syncthreads();

    for (int l = tid; l < 64 * 16; l += 256) {
        int row = l >> 4, c = l & 15;
        float4 v = ((const float4*)(emb + (size_t)sidx[row] * DIM))[c];
        float* dst = sm + row * 65 + c * 4;
        dst[0] = v.x; dst[1] = v.y; dst[2] = v.z; dst[3] = v.w;
    }
    __syncthreads();

    const int bb  = n0 >> 12;
    const int hw0 = n0 & 4095;
    float* ob = out + (size_t)bb * 262144 + hw0;
    for (int m = 0; m < 16; m++) {
        int idx = m * 256 + tid;
        int t = idx & 63, d = idx >> 6;
        ob[(size_t)d * 4096 + t] = sm[t * 65 + d];
    }
}

// scalars
__global__ void vq_final(float* __restrict__ out0)
{
    __shared__ float partial[K_CODES];
    int k = threadIdx.x;
    float p = (float)g_counts[k] * (1.0f / 131072.0f);
    partial[k] = p * logf(p + 1e-10f);
    __syncthreads();
    for (int s = 512; s > 0; s >>= 1) {
        if (k < s) partial[k] += partial[k + s];
        __syncthreads();
    }
    if (k == 0) {
        float mse = (float)(g_sse / 8388608.0);
        out0[0] = __fadd_rn(__fmul_rn(mse, 0.25f), mse);
        out0[1] = expf(-partial[0]);
    }
}

// ---------------------------------------------------------------------------
extern "C" void kernel_launch(void* const* d_in, const int* in_sizes, int n_in,
                              void* d_out, int out_size)
{
    const float* lat = (const float*)d_in[0];
    const float* emb = (const float*)d_in[1];
    float* out = (float*)d_out;
    (void)in_sizes; (void)n_in;

    cudaFuncSetAttribute(vq_main, cudaFuncAttributeMaxDynamicSharedMemorySize,
                         SMEM_FLOATS * (int)sizeof(float));

    int write_oh = (long long)out_size >= 2LL + 8388608LL + (long long)N_TOK * K_CODES;
    float* oh = out + 2 + 8388608;

    vq_zero  <<<1, 1024>>>();
    vq_sqnorm<<<1, 1024>>>(emb);
    vq_main  <<<1024, 512, SMEM_FLOATS * sizeof(float)>>>(lat, emb, oh, write_oh);
    vq_gather<<<N_TOK / 64, 256>>>(out + 2, emb);
    vq_final <<<1, 1024>>>(out);
}